// round 1
// baseline (speedup 1.0000x reference)
#include <cuda_runtime.h>
#include <math.h>

// ---------------------------------------------------------------------------
// StreamingSSMCell  (B=8192, D=1024, DCONV=4)
//   xz = x @ W_in^T + b_in          -> scratch [B, 2D]
//   elementwise: conv ring buffer, silu, decay recurrence, gate
//   out = g @ W_out^T + b_out       -> d_out[0 : B*D]
//   d_out layout: [ out (B*D) | h_new (B*D) | new_buf (B*D*DCONV) ]
// ---------------------------------------------------------------------------

#define MAX_B 8192
#define MAX_D 1024

// scratch for xz [B, 2D]; first half later reused (in-place) for gated g
__device__ float g_xz[(size_t)MAX_B * 2 * MAX_D];

// ----------------------------- fp32 SGEMM ---------------------------------
// C[m,n] = sum_k A[m,k] * Bm[n,k] + bias[n]
// A: [M,K] row-major lda, Bm: [N,K] row-major ldb (K contiguous for both).
// 128x128 block tile, BK=16, 256 threads, 8x8 per thread.
#define BM 128
#define BN 128
#define BK 16
#define TM 8
#define TN 8

__global__ __launch_bounds__(256, 2)
void sgemm_tn_bias(const float* __restrict__ A, int lda,
                   const float* __restrict__ Bm, int ldb,
                   const float* __restrict__ bias,
                   float* __restrict__ C, int ldc,
                   int K)
{
    __shared__ float As[BK][BM];
    __shared__ float Bs[BK][BN];

    const int tid = threadIdx.x;            // 0..255
    const int bm = blockIdx.y * BM;
    const int bn = blockIdx.x * BN;
    const int tx = tid & 15;                 // 0..15
    const int ty = tid >> 4;                 // 0..15

    const int lrow = tid >> 2;               // 0..63
    const int lcol = (tid & 3) * 4;          // 0,4,8,12

    float acc[TM][TN];
    #pragma unroll
    for (int i = 0; i < TM; i++)
        #pragma unroll
        for (int j = 0; j < TN; j++) acc[i][j] = 0.0f;

    for (int k0 = 0; k0 < K; k0 += BK) {
        #pragma unroll
        for (int r = 0; r < 2; r++) {
            const int row = lrow + r * 64;
            float4 va = *(const float4*)(A  + (size_t)(bm + row) * lda + k0 + lcol);
            As[lcol + 0][row] = va.x;
            As[lcol + 1][row] = va.y;
            As[lcol + 2][row] = va.z;
            As[lcol + 3][row] = va.w;
            float4 vb = *(const float4*)(Bm + (size_t)(bn + row) * ldb + k0 + lcol);
            Bs[lcol + 0][row] = vb.x;
            Bs[lcol + 1][row] = vb.y;
            Bs[lcol + 2][row] = vb.z;
            Bs[lcol + 3][row] = vb.w;
        }
        __syncthreads();

        #pragma unroll
        for (int k = 0; k < BK; k++) {
            float4 a0 = *(const float4*)&As[k][ty * TM + 0];
            float4 a1 = *(const float4*)&As[k][ty * TM + 4];
            float4 b0 = *(const float4*)&Bs[k][tx * TN + 0];
            float4 b1 = *(const float4*)&Bs[k][tx * TN + 4];
            const float ra[TM] = {a0.x, a0.y, a0.z, a0.w, a1.x, a1.y, a1.z, a1.w};
            const float rb[TN] = {b0.x, b0.y, b0.z, b0.w, b1.x, b1.y, b1.z, b1.w};
            #pragma unroll
            for (int i = 0; i < TM; i++)
                #pragma unroll
                for (int j = 0; j < TN; j++)
                    acc[i][j] = fmaf(ra[i], rb[j], acc[i][j]);
        }
        __syncthreads();
    }

    #pragma unroll
    for (int i = 0; i < TM; i++) {
        const int row = bm + ty * TM + i;
        #pragma unroll
        for (int j = 0; j < TN; j += 4) {
            const int col = bn + tx * TN + j;
            float4 v;
            v.x = acc[i][j + 0] + bias[col + 0];
            v.y = acc[i][j + 1] + bias[col + 1];
            v.z = acc[i][j + 2] + bias[col + 2];
            v.w = acc[i][j + 3] + bias[col + 3];
            *(float4*)(C + (size_t)row * ldc + col) = v;
        }
    }
}

// ------------------------ fused elementwise stage --------------------------
__device__ __forceinline__ float silu_f(float x) {
    return x / (1.0f + expf(-x));
}

__global__ void fused_elementwise(float* __restrict__ xz,        // [B, 2D]; [:, :D] overwritten with g
                                  const float* __restrict__ h,   // [B, D]
                                  const float* __restrict__ conv_buf, // [B, D, 4]
                                  const float* __restrict__ conv_w,   // [D, 4]
                                  const float* __restrict__ conv_b,   // [D]
                                  float* __restrict__ out_hnew,       // [B, D]
                                  float* __restrict__ out_newbuf,     // [B, D, 4]
                                  int B, int D)
{
    const int idx = blockIdx.x * blockDim.x + threadIdx.x;
    if (idx >= B * D) return;
    const int b = idx / D;
    const int d = idx - b * D;

    const float xi = xz[(size_t)b * 2 * D + d];
    const float z  = xz[(size_t)b * 2 * D + D + d];

    const float4 cb = *(const float4*)(conv_buf + (size_t)idx * 4);
    const float4 cw = *(const float4*)(conv_w + (size_t)d * 4);

    // shifted window: [cb.y, cb.z, cb.w, xi]
    float co = cb.y * cw.x + cb.z * cw.y + cb.w * cw.z + xi * cw.w + conv_b[d];
    co = silu_f(co);

    // decay[d] = exp(-1/tau), tau = exp(linspace(log(10), log(2000), D))
    const float lmin = 2.302585092994046f;    // log(10)
    const float lmax = 7.600902459542082f;    // log(2000)
    const float t = lmin + (float)d * (lmax - lmin) / (float)(D - 1);
    const float dec = expf(-expf(-t));        // exp(-1/exp(t)) = exp(-exp(-t))

    const float hn = dec * h[idx] + (1.0f - dec) * co;

    out_hnew[idx] = hn;
    float4 nb; nb.x = cb.y; nb.y = cb.z; nb.z = cb.w; nb.w = xi;
    *(float4*)(out_newbuf + (size_t)idx * 4) = nb;

    // gated activation, in place over x_inner slot (safe: same thread r/w)
    xz[(size_t)b * 2 * D + d] = hn * silu_f(z);
}

// ------------------------------- launch ------------------------------------
extern "C" void kernel_launch(void* const* d_in, const int* in_sizes, int n_in,
                              void* d_out, int out_size)
{
    const float* x        = (const float*)d_in[0];
    const float* h        = (const float*)d_in[1];
    const float* conv_buf = (const float*)d_in[2];
    const float* W_in     = (const float*)d_in[3];
    const float* b_in     = (const float*)d_in[4];
    const float* conv_w   = (const float*)d_in[5];
    const float* conv_b   = (const float*)d_in[6];
    const float* W_out    = (const float*)d_in[7];
    const float* b_out    = (const float*)d_in[8];

    const int D = in_sizes[6];            // conv_b has D elements
    const int B = in_sizes[0] / D;        // x is [B, D]
    const int twoD = in_sizes[4];         // b_in has 2D elements

    float* out      = (float*)d_out;                       // [B, D]
    float* out_hnew = out + (size_t)B * D;                 // [B, D]
    float* out_nbuf = out + (size_t)2 * B * D;             // [B, D, 4]

    float* xz = g_xz;

    // GEMM 1: xz = x @ W_in^T + b_in     [B, 2D]
    {
        dim3 grid(twoD / BN, B / BM);
        sgemm_tn_bias<<<grid, 256>>>(x, D, W_in, D, b_in, xz, twoD, D);
    }

    // elementwise fuse
    {
        const int n = B * D;
        fused_elementwise<<<(n + 255) / 256, 256>>>(
            xz, h, conv_buf, conv_w, conv_b, out_hnew, out_nbuf, B, D);
    }

    // GEMM 2: out = g @ W_out^T + b_out   (g lives in xz[:, :D], lda = 2D)
    {
        dim3 grid(D / BN, B / BM);
        sgemm_tn_bias<<<grid, 256>>>(xz, twoD, W_out, D, b_out, out, D, D);
    }
}

// round 3
// speedup vs baseline: 1.0446x; 1.0446x over previous
#include <cuda_runtime.h>
#include <math.h>
#include <stdint.h>

// ===========================================================================
// StreamingSSMCell (B=8192, D=1024, DCONV=4) — tf32 mma.sync version
// (tcgen05 unavailable: harness compiles PTX for plain sm_103, no 'a' features)
//   xz = x @ W_in^T + b_in        (tf32 mma.sync GEMM, RNA-rounded fragments)
//   elementwise: conv ring buffer, silu, decay recurrence, gate -> g
//   out = g @ W_out^T + b_out     (same GEMM)
//   d_out layout: [ out (B*D) | h_new (B*D) | new_buf (B*D*4) ]
// ===========================================================================

#define D_MODEL 1024
#define TWO_D   2048
#define BATCH   8192

// ------------------------------ scratch ------------------------------------
__device__ float g_xz[(size_t)BATCH * TWO_D];   // in_proj output
__device__ float g_g [(size_t)BATCH * D_MODEL]; // gated activation

// ------------------------------ GEMM config --------------------------------
#define BM 128
#define BN 256
#define BK 32
#define KPAD 36                         // 32 + 4 floats padding
#define NTHREADS 256
#define NSTAGE 3
#define A_TILE_WORDS (BM * KPAD)        // 4608
#define B_TILE_WORDS (BN * KPAD)        // 9216
#define STAGE_WORDS  (A_TILE_WORDS + B_TILE_WORDS)  // 13824
#define SMEM_BYTES   (NSTAGE * STAGE_WORDS * 4)     // 165888

// ------------------------------ PTX helpers --------------------------------
__device__ __forceinline__ uint32_t smem_u32(const void* p) {
    uint32_t a;
    asm("{ .reg .u64 t; cvta.to.shared.u64 t, %1; cvt.u32.u64 %0, t; }"
        : "=r"(a) : "l"(p));
    return a;
}

#define CP_ASYNC16(dst, src) \
    asm volatile("cp.async.cg.shared.global [%0], [%1], 16;" :: "r"(dst), "l"(src))
#define CP_ASYNC_COMMIT() asm volatile("cp.async.commit_group;" ::: "memory")
#define CP_ASYNC_WAIT1()  asm volatile("cp.async.wait_group 1;" ::: "memory")

__device__ __forceinline__ uint32_t f2tf32(float x) {
    uint32_t r;
    asm("cvt.rna.tf32.f32 %0, %1;" : "=r"(r) : "f"(x));
    return r;
}

#define MMA_TF32(c, a, b)                                                      \
    asm volatile("mma.sync.aligned.m16n8k8.row.col.f32.tf32.tf32.f32 "         \
        "{%0,%1,%2,%3}, {%4,%5,%6,%7}, {%8,%9}, {%0,%1,%2,%3};"                \
        : "+f"((c)[0]), "+f"((c)[1]), "+f"((c)[2]), "+f"((c)[3])               \
        : "r"((a)[0]), "r"((a)[1]), "r"((a)[2]), "r"((a)[3]),                  \
          "r"((b)[0]), "r"((b)[1]))

// ------------------------- tf32 mma.sync GEMM ------------------------------
// C[m,n] = sum_k A[m,k]*Bm[n,k] + bias[n]; A [M,K] lda, Bm [N,K] ldb (K-major)
// grid = (N/BN, M/BM), 256 threads; warp (wm, wn) owns a 64x64 subtile.
__global__ __launch_bounds__(NTHREADS, 1)
void gemm_tf32(const float* __restrict__ A, int lda,
               const float* __restrict__ Bm, int ldb,
               const float* __restrict__ bias,
               float* __restrict__ C, int ldc, int K)
{
    extern __shared__ float smem[];
    const uint32_t sbase = smem_u32(smem);
    const int tid  = threadIdx.x;
    const int lane = tid & 31;
    const int wid  = tid >> 5;
    const int wm = wid & 1;          // 0..1
    const int wn = wid >> 1;         // 0..3
    const int g  = lane >> 2;        // 0..7
    const int tg = lane & 3;         // 0..3
    const int m0 = blockIdx.y * BM;
    const int n0 = blockIdx.x * BN;

    const float* gA = A  + (size_t)m0 * lda;
    const float* gB = Bm + (size_t)n0 * ldb;

    float acc[4][8][4];
    #pragma unroll
    for (int i = 0; i < 4; i++)
        #pragma unroll
        for (int j = 0; j < 8; j++)
            #pragma unroll
            for (int r = 0; r < 4; r++) acc[i][j][r] = 0.0f;

    const int T = K / BK;

    #define LOAD_STAGE(t) do {                                                 \
        const uint32_t _s = sbase + ((t) % NSTAGE) * (STAGE_WORDS * 4);        \
        _Pragma("unroll")                                                      \
        for (int _q = 0; _q < 4; _q++) {                                       \
            const int _id = tid + _q * NTHREADS;                               \
            const int _r = _id >> 3, _c = _id & 7;                             \
            CP_ASYNC16(_s + _r * (KPAD * 4) + _c * 16,                         \
                       gA + (size_t)_r * lda + (size_t)(t) * BK + _c * 4);     \
        }                                                                      \
        const uint32_t _sb = _s + A_TILE_WORDS * 4;                            \
        _Pragma("unroll")                                                      \
        for (int _q = 0; _q < 8; _q++) {                                       \
            const int _id = tid + _q * NTHREADS;                               \
            const int _r = _id >> 3, _c = _id & 7;                             \
            CP_ASYNC16(_sb + _r * (KPAD * 4) + _c * 16,                        \
                       gB + (size_t)_r * ldb + (size_t)(t) * BK + _c * 4);     \
        }                                                                      \
        CP_ASYNC_COMMIT();                                                     \
    } while (0)

    LOAD_STAGE(0);
    LOAD_STAGE(1);

    for (int t = 0; t < T; t++) {
        CP_ASYNC_WAIT1();            // group t complete (in-order completion)
        __syncthreads();

        if (t + 2 < T) { LOAD_STAGE(t + 2); } else { CP_ASYNC_COMMIT(); }

        const float* fA = smem + (t % NSTAGE) * STAGE_WORDS;
        const float* fB = fA + A_TILE_WORDS;

        #pragma unroll
        for (int k0 = 0; k0 < BK; k0 += 8) {
            uint32_t af[4][4], bf[8][2];
            #pragma unroll
            for (int i = 0; i < 4; i++) {
                const int r = wm * 64 + i * 16 + g;
                af[i][0] = f2tf32(fA[(size_t)r       * KPAD + k0 + tg]);
                af[i][1] = f2tf32(fA[(size_t)(r + 8) * KPAD + k0 + tg]);
                af[i][2] = f2tf32(fA[(size_t)r       * KPAD + k0 + 4 + tg]);
                af[i][3] = f2tf32(fA[(size_t)(r + 8) * KPAD + k0 + 4 + tg]);
            }
            #pragma unroll
            for (int j = 0; j < 8; j++) {
                const int n = wn * 64 + j * 8 + g;
                bf[j][0] = f2tf32(fB[(size_t)n * KPAD + k0 + tg]);
                bf[j][1] = f2tf32(fB[(size_t)n * KPAD + k0 + 4 + tg]);
            }
            #pragma unroll
            for (int i = 0; i < 4; i++)
                #pragma unroll
                for (int j = 0; j < 8; j++)
                    MMA_TF32(acc[i][j], af[i], bf[j]);
        }
    }
    #undef LOAD_STAGE

    // epilogue: add bias, store fp32
    #pragma unroll
    for (int j = 0; j < 8; j++) {
        const int col = n0 + wn * 64 + j * 8 + tg * 2;
        const float2 bb = *(const float2*)(bias + col);
        #pragma unroll
        for (int i = 0; i < 4; i++) {
            const int r0 = m0 + wm * 64 + i * 16 + g;
            float2 v0; v0.x = acc[i][j][0] + bb.x; v0.y = acc[i][j][1] + bb.y;
            *(float2*)(C + (size_t)r0 * ldc + col) = v0;
            float2 v1; v1.x = acc[i][j][2] + bb.x; v1.y = acc[i][j][3] + bb.y;
            *(float2*)(C + (size_t)(r0 + 8) * ldc + col) = v1;
        }
    }
}

// ------------------------ fused elementwise stage ---------------------------
__device__ __forceinline__ float silu_f(float x) { return x / (1.0f + expf(-x)); }

__global__ void fused_elementwise(const float* __restrict__ xz,      // [B, 2D]
                                  const float* __restrict__ h,       // [B, D]
                                  const float* __restrict__ conv_buf,// [B, D, 4]
                                  const float* __restrict__ conv_w,  // [D, 4]
                                  const float* __restrict__ conv_b,  // [D]
                                  float* __restrict__ out_hnew,      // [B, D]
                                  float* __restrict__ out_newbuf,    // [B, D, 4]
                                  float* __restrict__ g_out,         // [B, D]
                                  int B, int D)
{
    const int idx = blockIdx.x * blockDim.x + threadIdx.x;
    if (idx >= B * D) return;
    const int b = idx / D;
    const int d = idx - b * D;

    const float xi = xz[(size_t)b * 2 * D + d];
    const float z  = xz[(size_t)b * 2 * D + D + d];

    const float4 cb = *(const float4*)(conv_buf + (size_t)idx * 4);
    const float4 cw = *(const float4*)(conv_w + (size_t)d * 4);

    float co = cb.y * cw.x + cb.z * cw.y + cb.w * cw.z + xi * cw.w + conv_b[d];
    co = silu_f(co);

    // decay[d] = exp(-1/tau), tau = exp(linspace(log(10), log(2000), D))
    const float lmin = 2.302585092994046f;
    const float lmax = 7.600902459542082f;
    const float t = lmin + (float)d * (lmax - lmin) / (float)(D - 1);
    const float dec = expf(-expf(-t));

    const float hn = dec * h[idx] + (1.0f - dec) * co;

    out_hnew[idx] = hn;
    float4 nb; nb.x = cb.y; nb.y = cb.z; nb.z = cb.w; nb.w = xi;
    *(float4*)(out_newbuf + (size_t)idx * 4) = nb;

    g_out[idx] = hn * silu_f(z);
}

// ------------------------------- launch ------------------------------------
extern "C" void kernel_launch(void* const* d_in, const int* in_sizes, int n_in,
                              void* d_out, int out_size)
{
    const float* x        = (const float*)d_in[0];
    const float* h        = (const float*)d_in[1];
    const float* conv_buf = (const float*)d_in[2];
    const float* W_in     = (const float*)d_in[3];
    const float* b_in     = (const float*)d_in[4];
    const float* conv_w   = (const float*)d_in[5];
    const float* conv_b   = (const float*)d_in[6];
    const float* W_out    = (const float*)d_in[7];
    const float* b_out    = (const float*)d_in[8];

    const int D = in_sizes[6];
    const int B = in_sizes[0] / D;
    const int twoD = in_sizes[4];

    float* out      = (float*)d_out;
    float* out_hnew = out + (size_t)B * D;
    float* out_nbuf = out + (size_t)2 * B * D;

    float* xz = g_xz;
    float* gg = g_g;

    cudaFuncSetAttribute(gemm_tf32, cudaFuncAttributeMaxDynamicSharedMemorySize,
                         SMEM_BYTES);

    // GEMM1: xz = x @ W_in^T + b_in   [B, 2D]
    {
        dim3 grid(twoD / BN, B / BM);
        gemm_tf32<<<grid, NTHREADS, SMEM_BYTES>>>(x, D, W_in, D, b_in, xz, twoD, D);
    }

    // fused elementwise
    {
        const int n = B * D;
        fused_elementwise<<<(n + 255) / 256, 256>>>(
            xz, h, conv_buf, conv_w, conv_b, out_hnew, out_nbuf, gg, B, D);
    }

    // GEMM2: out = g @ W_out^T + b_out  [B, D]
    {
        dim3 grid(D / BN, B / BM);
        gemm_tf32<<<grid, NTHREADS, SMEM_BYTES>>>(gg, D, W_out, D, b_out, out, D, D);
    }
}

// round 4
// speedup vs baseline: 1.0672x; 1.0216x over previous
#include <cuda_runtime.h>
#include <math.h>
#include <stdint.h>

// ===========================================================================
// StreamingSSMCell (B=8192, D=1024, DCONV=4) — tf32 mma.sync + ldmatrix
//   xz = x @ W_in^T + b_in        (tf32 mma.sync GEMM, RNA-rounded fragments)
//   elementwise: conv ring buffer, silu, decay recurrence, gate -> g
//   out = g @ W_out^T + b_out
//   d_out layout: [ out (B*D) | h_new (B*D) | new_buf (B*D*4) ]
// ===========================================================================

#define D_MODEL 1024
#define TWO_D   2048
#define BATCH   8192

__device__ float g_xz[(size_t)BATCH * TWO_D];
__device__ float g_g [(size_t)BATCH * D_MODEL];

// ------------------------------ GEMM config --------------------------------
#define BM 128
#define BN 256
#define BK 32
#define KPAD 36                          // 32 + 4 floats pad (row = 144B)
#define NTHREADS 512                     // 16 warps: wm(2) x wn(8), 64x32 each
#define NSTAGE 3
#define A_TILE_WORDS (BM * KPAD)
#define B_TILE_WORDS (BN * KPAD)
#define STAGE_WORDS  (A_TILE_WORDS + B_TILE_WORDS)
#define SMEM_BYTES   (NSTAGE * STAGE_WORDS * 4)      // 165888

// ------------------------------ PTX helpers --------------------------------
__device__ __forceinline__ uint32_t smem_u32(const void* p) {
    uint32_t a;
    asm("{ .reg .u64 t; cvta.to.shared.u64 t, %1; cvt.u32.u64 %0, t; }"
        : "=r"(a) : "l"(p));
    return a;
}

#define CP_ASYNC16(dst, src) \
    asm volatile("cp.async.cg.shared.global [%0], [%1], 16;" :: "r"(dst), "l"(src))
#define CP_ASYNC_COMMIT() asm volatile("cp.async.commit_group;" ::: "memory")
#define CP_ASYNC_WAIT1()  asm volatile("cp.async.wait_group 1;" ::: "memory")

__device__ __forceinline__ uint32_t rna(uint32_t x) {
    uint32_t r;
    asm("cvt.rna.tf32.f32 %0, %1;" : "=r"(r) : "f"(__uint_as_float(x)));
    return r;
}

#define LDSM_X4(r0, r1, r2, r3, addr)                                          \
    asm volatile("ldmatrix.sync.aligned.m8n8.x4.shared.b16 {%0,%1,%2,%3}, [%4];" \
        : "=r"(r0), "=r"(r1), "=r"(r2), "=r"(r3) : "r"(addr))

#define MMA_TF32(c, a, b)                                                      \
    asm volatile("mma.sync.aligned.m16n8k8.row.col.f32.tf32.tf32.f32 "         \
        "{%0,%1,%2,%3}, {%4,%5,%6,%7}, {%8,%9}, {%0,%1,%2,%3};"                \
        : "+f"((c)[0]), "+f"((c)[1]), "+f"((c)[2]), "+f"((c)[3])               \
        : "r"((a)[0]), "r"((a)[1]), "r"((a)[2]), "r"((a)[3]),                  \
          "r"((b)[0]), "r"((b)[1]))

// ------------------------- tf32 mma.sync GEMM ------------------------------
// C[m,n] = sum_k A[m,k]*Bm[n,k] + bias[n]; A [M,K] lda, Bm [N,K] ldb, K-major.
// grid = (N/BN, M/BM), 512 threads. Warp (wm, wn) owns 64x32.
__global__ __launch_bounds__(NTHREADS, 1)
void gemm_tf32(const float* __restrict__ A, int lda,
               const float* __restrict__ Bm, int ldb,
               const float* __restrict__ bias,
               float* __restrict__ C, int ldc, int K)
{
    extern __shared__ float smem[];
    const uint32_t sbase = smem_u32(smem);
    const int tid  = threadIdx.x;
    const int lane = tid & 31;
    const int wid  = tid >> 5;
    const int wm = wid >> 3;             // 0..1  (64-row slab)
    const int wn = wid & 7;              // 0..7  (32-col slab)
    const int g  = lane >> 2;
    const int tg = lane & 3;
    const int m0 = blockIdx.y * BM;
    const int n0 = blockIdx.x * BN;

    const float* gA = A  + (size_t)m0 * lda;
    const float* gB = Bm + (size_t)n0 * ldb;

    // ldmatrix per-lane byte offsets (within stage), computed once.
    // A tile i: m0 = rows(lane&15)+i*16+wm*64, colchunk (lane>>4)*4 floats
    uint32_t a_off[4];
    #pragma unroll
    for (int i = 0; i < 4; i++) {
        const int row = wm * 64 + i * 16 + (lane & 15);
        a_off[i] = (uint32_t)(row * KPAD + ((lane >> 4) << 2)) * 4u;
    }
    // B pair jj: rows jj*16 + (lane>>4)*8 + (lane&7), colchunk ((lane>>3)&1)*4
    uint32_t b_off[2];
    #pragma unroll
    for (int jj = 0; jj < 2; jj++) {
        const int row = wn * 32 + jj * 16 + ((lane >> 4) << 3) + (lane & 7);
        b_off[jj] = (uint32_t)(row * KPAD + (((lane >> 3) & 1) << 2)) * 4u
                    + (uint32_t)(A_TILE_WORDS * 4);
    }

    float acc[4][4][4];
    #pragma unroll
    for (int i = 0; i < 4; i++)
        #pragma unroll
        for (int j = 0; j < 4; j++)
            #pragma unroll
            for (int r = 0; r < 4; r++) acc[i][j][r] = 0.0f;

    const int T = K / BK;

    #define LOAD_STAGE(t) do {                                                 \
        const uint32_t _s = sbase + ((t) % NSTAGE) * (STAGE_WORDS * 4);        \
        _Pragma("unroll")                                                      \
        for (int _q = 0; _q < 2; _q++) {                                       \
            const int _id = tid + _q * NTHREADS;                               \
            const int _r = _id >> 3, _c = _id & 7;                             \
            CP_ASYNC16(_s + _r * (KPAD * 4) + _c * 16,                         \
                       gA + (size_t)_r * lda + (size_t)(t) * BK + _c * 4);     \
        }                                                                      \
        const uint32_t _sb = _s + A_TILE_WORDS * 4;                            \
        _Pragma("unroll")                                                      \
        for (int _q = 0; _q < 4; _q++) {                                       \
            const int _id = tid + _q * NTHREADS;                               \
            const int _r = _id >> 3, _c = _id & 7;                             \
            CP_ASYNC16(_sb + _r * (KPAD * 4) + _c * 16,                        \
                       gB + (size_t)_r * ldb + (size_t)(t) * BK + _c * 4);     \
        }                                                                      \
        CP_ASYNC_COMMIT();                                                     \
    } while (0)

    LOAD_STAGE(0);
    LOAD_STAGE(1);

    for (int t = 0; t < T; t++) {
        CP_ASYNC_WAIT1();
        __syncthreads();

        if (t + 2 < T) { LOAD_STAGE(t + 2); } else { CP_ASYNC_COMMIT(); }

        const uint32_t st = sbase + (t % NSTAGE) * (STAGE_WORDS * 4);

        #pragma unroll
        for (int k0 = 0; k0 < BK; k0 += 8) {
            const uint32_t kb = (uint32_t)(k0 * 4);
            uint32_t af[4][4], bf[4][2];
            #pragma unroll
            for (int i = 0; i < 4; i++) {
                LDSM_X4(af[i][0], af[i][1], af[i][2], af[i][3],
                        st + a_off[i] + kb);
            }
            #pragma unroll
            for (int jj = 0; jj < 2; jj++) {
                LDSM_X4(bf[jj * 2][0], bf[jj * 2][1],
                        bf[jj * 2 + 1][0], bf[jj * 2 + 1][1],
                        st + b_off[jj] + kb);
            }
            #pragma unroll
            for (int i = 0; i < 4; i++)
                #pragma unroll
                for (int q = 0; q < 4; q++) af[i][q] = rna(af[i][q]);
            #pragma unroll
            for (int j = 0; j < 4; j++) {
                bf[j][0] = rna(bf[j][0]);
                bf[j][1] = rna(bf[j][1]);
            }
            #pragma unroll
            for (int i = 0; i < 4; i++)
                #pragma unroll
                for (int j = 0; j < 4; j++)
                    MMA_TF32(acc[i][j], af[i], bf[j]);
        }
    }
    #undef LOAD_STAGE

    // epilogue: add bias, store fp32
    #pragma unroll
    for (int j = 0; j < 4; j++) {
        const int col = n0 + wn * 32 + j * 8 + tg * 2;
        const float2 bb = *(const float2*)(bias + col);
        #pragma unroll
        for (int i = 0; i < 4; i++) {
            const int r0 = m0 + wm * 64 + i * 16 + g;
            float2 v0; v0.x = acc[i][j][0] + bb.x; v0.y = acc[i][j][1] + bb.y;
            *(float2*)(C + (size_t)r0 * ldc + col) = v0;
            float2 v1; v1.x = acc[i][j][2] + bb.x; v1.y = acc[i][j][3] + bb.y;
            *(float2*)(C + (size_t)(r0 + 8) * ldc + col) = v1;
        }
    }
}

// ------------------------ fused elementwise stage ---------------------------
__device__ __forceinline__ float silu_f(float x) { return x / (1.0f + expf(-x)); }

__global__ void fused_elementwise(const float* __restrict__ xz,
                                  const float* __restrict__ h,
                                  const float* __restrict__ conv_buf,
                                  const float* __restrict__ conv_w,
                                  const float* __restrict__ conv_b,
                                  float* __restrict__ out_hnew,
                                  float* __restrict__ out_newbuf,
                                  float* __restrict__ g_out,
                                  int B, int D)
{
    const int idx = blockIdx.x * blockDim.x + threadIdx.x;
    if (idx >= B * D) return;
    const int b = idx / D;
    const int d = idx - b * D;

    const float xi = xz[(size_t)b * 2 * D + d];
    const float z  = xz[(size_t)b * 2 * D + D + d];

    const float4 cb = *(const float4*)(conv_buf + (size_t)idx * 4);
    const float4 cw = *(const float4*)(conv_w + (size_t)d * 4);

    float co = cb.y * cw.x + cb.z * cw.y + cb.w * cw.z + xi * cw.w + conv_b[d];
    co = silu_f(co);

    const float lmin = 2.302585092994046f;   // log(10)
    const float lmax = 7.600902459542082f;   // log(2000)
    const float t = lmin + (float)d * (lmax - lmin) / (float)(D - 1);
    const float dec = expf(-expf(-t));

    const float hn = dec * h[idx] + (1.0f - dec) * co;

    out_hnew[idx] = hn;
    float4 nb; nb.x = cb.y; nb.y = cb.z; nb.z = cb.w; nb.w = xi;
    *(float4*)(out_newbuf + (size_t)idx * 4) = nb;

    g_out[idx] = hn * silu_f(z);
}

// ------------------------------- launch ------------------------------------
extern "C" void kernel_launch(void* const* d_in, const int* in_sizes, int n_in,
                              void* d_out, int out_size)
{
    const float* x        = (const float*)d_in[0];
    const float* h        = (const float*)d_in[1];
    const float* conv_buf = (const float*)d_in[2];
    const float* W_in     = (const float*)d_in[3];
    const float* b_in     = (const float*)d_in[4];
    const float* conv_w   = (const float*)d_in[5];
    const float* conv_b   = (const float*)d_in[6];
    const float* W_out    = (const float*)d_in[7];
    const float* b_out    = (const float*)d_in[8];

    const int D = in_sizes[6];
    const int B = in_sizes[0] / D;
    const int twoD = in_sizes[4];

    float* out      = (float*)d_out;
    float* out_hnew = out + (size_t)B * D;
    float* out_nbuf = out + (size_t)2 * B * D;

    float* xz = g_xz;
    float* gg = g_g;

    cudaFuncSetAttribute(gemm_tf32, cudaFuncAttributeMaxDynamicSharedMemorySize,
                         SMEM_BYTES);

    // GEMM1: xz = x @ W_in^T + b_in   [B, 2D]
    {
        dim3 grid(twoD / BN, B / BM);
        gemm_tf32<<<grid, NTHREADS, SMEM_BYTES>>>(x, D, W_in, D, b_in, xz, twoD, D);
    }

    // fused elementwise
    {
        const int n = B * D;
        fused_elementwise<<<(n + 255) / 256, 256>>>(
            xz, h, conv_buf, conv_w, conv_b, out_hnew, out_nbuf, gg, B, D);
    }

    // GEMM2: out = g @ W_out^T + b_out  [B, D]
    {
        dim3 grid(D / BN, B / BM);
        gemm_tf32<<<grid, NTHREADS, SMEM_BYTES>>>(gg, D, W_out, D, b_out, out, D, D);
    }
}